// round 1
// baseline (speedup 1.0000x reference)
#include <cuda_runtime.h>

// Problem shape (fixed by setup_inputs): B=32, N=65536, T=64, HIDDEN=16.
#define BB     32
#define NN     65536
#define TT     64
#define WORDS  (NN / 64)   // 1024 u64 words per row

// Packed bit field for steps t=1..63: (T-1) x B x WORDS u64 = ~16.5 MB scratch.
__device__ unsigned long long g_bits[(TT - 1) * BB * WORDS];

// ---------------------------------------------------------------------------
// Phase 1: binary cellular automaton.
// One CTA per batch row, 1024 threads, each thread owns one 64-bit word
// (64 cells). Field lives in shared memory (double-buffered -> one barrier
// per step). The controller MLP collapses to an 8-entry truth table computed
// once per CTA by threads 0..7.
// ---------------------------------------------------------------------------
__global__ __launch_bounds__(WORDS) void ca_kernel(
    const float* __restrict__ f0,
    const float* __restrict__ W1,   // (3,16) row-major
    const float* __restrict__ b1,   // (16,)
    const float* __restrict__ W2,   // (16,1)
    const float* __restrict__ b2)   // (1,)
{
    __shared__ unsigned long long buf[2][WORDS];
    __shared__ unsigned long long msk[8];

    const int b = blockIdx.x;
    const int i = threadIdx.x;

    // Truth table: pattern p = (l<<2)|(c<<1)|r; next bit = (logit(p) > 0).
    if (i < 8) {
        const float l = (float)((i >> 2) & 1);
        const float c = (float)((i >> 1) & 1);
        const float r = (float)(i & 1);
        float logit = b2[0];
#pragma unroll
        for (int h = 0; h < 16; h++) {
            float v = fmaf(l, W1[h], fmaf(c, W1[16 + h], fmaf(r, W1[32 + h], b1[h])));
            logit = fmaf(W2[h], fmaxf(v, 0.0f), logit);
        }
        msk[i] = (logit > 0.0f) ? ~0ULL : 0ULL;
    }

    // Pack the initial field: thread i owns cells [64*i, 64*i+64).
    const float4* row = (const float4*)(f0 + (size_t)b * NN);
    unsigned long long w = 0ULL;
#pragma unroll
    for (int k = 0; k < 16; k++) {
        float4 v = row[i * 16 + k];
        unsigned long long q = 0ULL;
        if (v.x > 0.5f) q |= 1ULL;
        if (v.y > 0.5f) q |= 2ULL;
        if (v.z > 0.5f) q |= 4ULL;
        if (v.w > 0.5f) q |= 8ULL;
        w |= q << (4 * k);
    }
    buf[0][i] = w;
    __syncthreads();

    const unsigned long long m0 = msk[0], m1 = msk[1], m2 = msk[2], m3 = msk[3];
    const unsigned long long m4 = msk[4], m5 = msk[5], m6 = msk[6], m7 = msk[7];

    int s = 0;
    for (int t = 1; t < TT; t++) {
        const unsigned long long c = buf[s][i];
        const unsigned long long p = (i > 0)         ? buf[s][i - 1] : 0ULL;
        const unsigned long long n = (i < WORDS - 1) ? buf[s][i + 1] : 0ULL;
        // Left/right neighbor bit-planes ('zeros' boundary handled by p/n=0).
        const unsigned long long L = (c << 1) | (p >> 63);
        const unsigned long long R = (c >> 1) | (n << 63);
        const unsigned long long Ln = ~L, Cn = ~c, Rn = ~R;
        const unsigned long long nx =
            (Ln & Cn & Rn & m0) | (Ln & Cn & R & m1) |
            (Ln & c  & Rn & m2) | (Ln & c  & R & m3) |
            (L  & Cn & Rn & m4) | (L  & Cn & R & m5) |
            (L  & c  & Rn & m6) | (L  & c  & R & m7);

        g_bits[((size_t)(t - 1) * BB + b) * WORDS + i] = nx;
        buf[s ^ 1][i] = nx;
        s ^= 1;
        __syncthreads();
    }
}

// ---------------------------------------------------------------------------
// Phase 2: unpack bits -> fp32 output for t = 1..63.
// One thread per packed byte: 1B read (L2-resident scratch), 32B written
// (two float4). Fully parallel; pure store-bandwidth bound.
// ---------------------------------------------------------------------------
__global__ __launch_bounds__(256) void unpack_kernel(float* __restrict__ out) {
    const unsigned int tid = blockIdx.x * blockDim.x + threadIdx.x;
    const unsigned char* bytes = (const unsigned char*)g_bits;
    const unsigned int v = bytes[tid];

    // Byte tid covers flat bit index 8*tid of the (t-1, b, cell) space;
    // output offset skips the t=0 slab (B*N floats).
    float4* o = (float4*)(out + (size_t)BB * NN + (size_t)tid * 8);
    float4 a, c;
    a.x = (v & 1u)    ? 1.0f : 0.0f;
    a.y = (v & 2u)    ? 1.0f : 0.0f;
    a.z = (v & 4u)    ? 1.0f : 0.0f;
    a.w = (v & 8u)    ? 1.0f : 0.0f;
    c.x = (v & 16u)   ? 1.0f : 0.0f;
    c.y = (v & 32u)   ? 1.0f : 0.0f;
    c.z = (v & 64u)   ? 1.0f : 0.0f;
    c.w = (v & 128u)  ? 1.0f : 0.0f;
    o[0] = a;
    o[1] = c;
}

extern "C" void kernel_launch(void* const* d_in, const int* in_sizes, int n_in,
                              void* d_out, int out_size) {
    const float* f0 = (const float*)d_in[0];
    const float* W1 = (const float*)d_in[1];
    const float* b1 = (const float*)d_in[2];
    const float* W2 = (const float*)d_in[3];
    const float* b2 = (const float*)d_in[4];
    float* out = (float*)d_out;

    // out[0] = f0 verbatim.
    cudaMemcpyAsync(out, f0, (size_t)BB * NN * sizeof(float),
                    cudaMemcpyDeviceToDevice, 0);

    // Steps 1..63 as a packed-bit CA.
    ca_kernel<<<BB, WORDS>>>(f0, W1, b1, W2, b2);

    // Bits -> fp32.
    const int total_bytes = (TT - 1) * BB * (NN / 8);   // 16,515,072
    unpack_kernel<<<total_bytes / 256, 256>>>(out);
}

// round 2
// speedup vs baseline: 2.2609x; 2.2609x over previous
#include <cuda_runtime.h>

// Shape fixed by setup_inputs: B=32, N=65536, T=64, HIDDEN=16.
#define BB      32
#define NN      65536
#define TT      64
#define CHUNKS  32                 // chunks per row
#define CWORDS  32                 // u64 words per chunk (2048 cells)
#define FULLM   0xFFFFFFFFu

typedef unsigned long long u64;

// 3-input mux tree over constant masks: next = msk[L*4 + C*2 + R] per bit.
__device__ __forceinline__ u64 mux3(u64 L, u64 C, u64 R,
                                    u64 m0, u64 m1, u64 m2, u64 m3,
                                    u64 m4, u64 m5, u64 m6, u64 m7) {
    u64 x0 = (R & m1) | (~R & m0);
    u64 x1 = (R & m3) | (~R & m2);
    u64 x2 = (R & m5) | (~R & m4);
    u64 x3 = (R & m7) | (~R & m6);
    u64 y0 = (C & x1) | (~C & x0);
    u64 y1 = (C & x3) | (~C & x2);
    return (L & y1) | (~L & y0);
}

__device__ __forceinline__ u64 pack_word(const float* __restrict__ p) {
    u64 w = 0ULL;
    const float4* p4 = (const float4*)p;
#pragma unroll
    for (int k = 0; k < 16; k++) {
        float4 v = p4[k];
        u64 q = 0ULL;
        if (v.x > 0.5f) q |= 1ULL;
        if (v.y > 0.5f) q |= 2ULL;
        if (v.z > 0.5f) q |= 4ULL;
        if (v.w > 0.5f) q |= 8ULL;
        w |= q << (4 * k);
    }
    return w;
}

// One warp per (row, chunk). Each lane owns one u64 word (64 cells) in a
// register; neighbor words come via warp shuffle. Lanes 0/31 additionally
// evolve one halo word each — 63 steps < 64 bits, so garbage from beyond the
// halo never reaches the chunk. Every step writes the fp32 slab for this
// chunk, coalesced via a 2-source broadcast shuffle.
__global__ __launch_bounds__(256) void fused_kernel(
    const float* __restrict__ f0,
    const float* __restrict__ W1,   // (3,16)
    const float* __restrict__ b1,   // (16,)
    const float* __restrict__ W2,   // (16,1)
    const float* __restrict__ b2,   // (1,)
    float* __restrict__ out)
{
    __shared__ u64 smsk[8];
    const int tid = threadIdx.x;

    // Collapse the MLP controller to an 8-entry truth table.
    if (tid < 8) {
        const float l = (float)((tid >> 2) & 1);
        const float c = (float)((tid >> 1) & 1);
        const float r = (float)(tid & 1);
        float logit = b2[0];
#pragma unroll
        for (int h = 0; h < 16; h++) {
            float v = fmaf(l, W1[h], fmaf(c, W1[16 + h], fmaf(r, W1[32 + h], b1[h])));
            logit = fmaf(W2[h], fmaxf(v, 0.0f), logit);
        }
        smsk[tid] = (logit > 0.0f) ? ~0ULL : 0ULL;
    }
    __syncthreads();

    const u64 m0 = smsk[0], m1 = smsk[1], m2 = smsk[2], m3 = smsk[3];
    const u64 m4 = smsk[4], m5 = smsk[5], m6 = smsk[6], m7 = smsk[7];

    const int gw   = blockIdx.x * 8 + (tid >> 5);   // global warp id 0..1023
    const int lane = tid & 31;
    const int row  = gw >> 5;                       // batch row
    const int ch   = gw & (CHUNKS - 1);             // chunk within row
    const bool first = (ch == 0), last = (ch == CHUNKS - 1);

    const size_t rowoff = (size_t)row * NN;
    const int cell0 = ch * (CWORDS * 64);           // first cell of chunk

    // ---- t = 0 slab: verbatim copy of f0 for this chunk (coalesced) ----
    const float4* src4 = (const float4*)(f0 + rowoff + cell0);
    float4* dst4 = (float4*)(out + rowoff + cell0);
#pragma unroll
    for (int k = 0; k < 16; k++) {
        __stcs(dst4 + k * 32 + lane, __ldg(src4 + k * 32 + lane));
    }

    // ---- pack this lane's word + halo words ----
    u64 cur = pack_word(f0 + rowoff + cell0 + lane * 64);
    u64 hl = 0ULL, hr = 0ULL;
    if (lane == 0 && !first)
        hl = pack_word(f0 + rowoff + cell0 - 64);
    if (lane == 31 && !last)
        hr = pack_word(f0 + rowoff + cell0 + CWORDS * 64);

    // ---- 63 CA steps, writing the fp32 slab each step ----
    for (int t = 1; t < TT; t++) {
        u64 p = __shfl_up_sync(FULLM, cur, 1);
        u64 n = __shfl_down_sync(FULLM, cur, 1);
        if (lane == 0)  p = hl;
        if (lane == 31) n = hr;

        const u64 L = (cur << 1) | (p >> 63);
        const u64 R = (cur >> 1) | (n << 63);
        const u64 nx = mux3(L, cur, R, m0, m1, m2, m3, m4, m5, m6, m7);

        // Evolve halo words (lanes 0/31 only; true row boundary stays 0).
        if (lane == 0 && !first) {
            const u64 hL = hl << 1;                       // beyond-halo = garbage-as-0
            const u64 hR = (hl >> 1) | (cur << 63);
            hl = mux3(hL, hl, hR, m0, m1, m2, m3, m4, m5, m6, m7);
        }
        if (lane == 31 && !last) {
            const u64 hL = (hr << 1) | (cur >> 63);
            const u64 hR = hr >> 1;
            hr = mux3(hL, hr, hR, m0, m1, m2, m3, m4, m5, m6, m7);
        }
        cur = nx;

        // Coalesced fp32 output: float4 #idx of the chunk comes from word
        // idx>>4 (only 2 distinct shuffle sources per iteration -> broadcast).
        float4* ot = (float4*)(out + (size_t)t * (BB * NN) + rowoff + cell0);
#pragma unroll
        for (int k = 0; k < 16; k++) {
            const int idx = k * 32 + lane;
            const u64 w = __shfl_sync(FULLM, cur, idx >> 4);
            const unsigned int nib = (unsigned int)(w >> ((idx & 15) * 4)) & 0xFu;
            float4 v;
            v.x = (nib & 1u) ? 1.0f : 0.0f;
            v.y = (nib & 2u) ? 1.0f : 0.0f;
            v.z = (nib & 4u) ? 1.0f : 0.0f;
            v.w = (nib & 8u) ? 1.0f : 0.0f;
            __stcs(ot + idx, v);
        }
    }
}

extern "C" void kernel_launch(void* const* d_in, const int* in_sizes, int n_in,
                              void* d_out, int out_size) {
    const float* f0 = (const float*)d_in[0];
    const float* W1 = (const float*)d_in[1];
    const float* b1 = (const float*)d_in[2];
    const float* W2 = (const float*)d_in[3];
    const float* b2 = (const float*)d_in[4];
    float* out = (float*)d_out;

    // 32 rows x 32 chunks = 1024 warps; 8 warps per CTA -> 128 CTAs.
    fused_kernel<<<128, 256>>>(f0, W1, b1, W2, b2, out);
}